// round 2
// baseline (speedup 1.0000x reference)
#include <cuda_runtime.h>
#include <math.h>

#define BB 4
#define TT 2048
#define HH 1024
#define NH 16
#define HD 64
#define H3 3072

// Scratch (allocation-free rule: __device__ globals)
__device__ float g_qkv[(size_t)BB * TT * H3];   // (B,T,3H)
__device__ float g_att[(size_t)BB * TT * HH];   // (B,T,H)
__device__ int   g_len[BB];

// ---------------------------------------------------------------------------
// Per-batch valid-prefix length from the mask. Mask dtype is detected from
// the first 4 bytes (len >= T/2 >= 1 guarantees element 0..3 are all 1):
//   0x01010101 -> 1-byte bool/uint8
//   0x00000001 -> int32
//   0x3F800000 -> float32
// ---------------------------------------------------------------------------
__global__ void len_kernel(const unsigned char* __restrict__ mask) {
    __shared__ int sred[256];
    const unsigned int w0 = *(const unsigned int*)mask;
    const int b = blockIdx.x;
    int cnt = 0;
    if (w0 == 0x01010101u) {            // uint8
        for (int t = threadIdx.x; t < TT; t += 256)
            cnt += (mask[(size_t)b * TT + t] != 0) ? 1 : 0;
    } else if (w0 == 0x3F800000u) {     // float32
        const float* m = (const float*)mask;
        for (int t = threadIdx.x; t < TT; t += 256)
            cnt += (m[(size_t)b * TT + t] != 0.f) ? 1 : 0;
    } else {                            // int32 (covers w0 == 1)
        const int* m = (const int*)mask;
        for (int t = threadIdx.x; t < TT; t += 256)
            cnt += (m[(size_t)b * TT + t] != 0) ? 1 : 0;
    }
    sred[threadIdx.x] = cnt;
    __syncthreads();
    for (int s = 128; s > 0; s >>= 1) {
        if (threadIdx.x < s) sred[threadIdx.x] += sred[threadIdx.x + s];
        __syncthreads();
    }
    if (threadIdx.x == 0) g_len[b] = sred[0];
}

// ---------------------------------------------------------------------------
// SGEMM: C(M,N) = A(M,K) @ W(K,N) + bias(N). 128x128x8 tile, 256 thr, 8x8/thr.
// ---------------------------------------------------------------------------
__global__ __launch_bounds__(256) void sgemm_bias(
    const float* __restrict__ A, const float* __restrict__ W,
    const float* __restrict__ bias, float* __restrict__ C,
    int M, int N, int K)
{
    __shared__ float As[8][128];   // transposed A tile: As[k][m]
    __shared__ float Ws[8][128];   // natural W tile:    Ws[k][n]

    const int tid = threadIdx.x;
    const int tx = tid & 15;
    const int ty = tid >> 4;
    const int brow = blockIdx.y * 128;
    const int bcol = blockIdx.x * 128;

    const int arow = tid >> 1;
    const int acol = (tid & 1) * 4;
    const float* Aptr = A + (size_t)(brow + arow) * K + acol;
    const int wkr = tid >> 5;
    const int wc  = (tid & 31) * 4;
    const float* Wptr = W + (size_t)wkr * N + bcol + wc;

    float acc[8][8];
    #pragma unroll
    for (int i = 0; i < 8; i++)
        #pragma unroll
        for (int j = 0; j < 8; j++) acc[i][j] = 0.f;

    for (int k0 = 0; k0 < K; k0 += 8) {
        float4 a4 = *(const float4*)(Aptr + k0);
        As[acol + 0][arow] = a4.x;
        As[acol + 1][arow] = a4.y;
        As[acol + 2][arow] = a4.z;
        As[acol + 3][arow] = a4.w;
        float4 w4 = *(const float4*)(Wptr + (size_t)k0 * N);
        *(float4*)&Ws[wkr][wc] = w4;
        __syncthreads();

        #pragma unroll
        for (int k = 0; k < 8; k++) {
            float4 a0 = *(const float4*)&As[k][ty * 8];
            float4 a1 = *(const float4*)&As[k][ty * 8 + 4];
            float4 b0 = *(const float4*)&Ws[k][tx * 8];
            float4 b1 = *(const float4*)&Ws[k][tx * 8 + 4];
            float ra[8] = {a0.x, a0.y, a0.z, a0.w, a1.x, a1.y, a1.z, a1.w};
            float rb[8] = {b0.x, b0.y, b0.z, b0.w, b1.x, b1.y, b1.z, b1.w};
            #pragma unroll
            for (int i = 0; i < 8; i++)
                #pragma unroll
                for (int j = 0; j < 8; j++)
                    acc[i][j] += ra[i] * rb[j];
        }
        __syncthreads();
    }

    float bb[8];
    #pragma unroll
    for (int j = 0; j < 8; j++) bb[j] = bias[bcol + tx * 8 + j];

    #pragma unroll
    for (int i = 0; i < 8; i++) {
        float* crow = C + (size_t)(brow + ty * 8 + i) * N + bcol + tx * 8;
        float4 c0 = {acc[i][0] + bb[0], acc[i][1] + bb[1],
                     acc[i][2] + bb[2], acc[i][3] + bb[3]};
        float4 c1 = {acc[i][4] + bb[4], acc[i][5] + bb[5],
                     acc[i][6] + bb[6], acc[i][7] + bb[7]};
        *(float4*)(crow)     = c0;
        *(float4*)(crow + 4) = c1;
    }
}

// ---------------------------------------------------------------------------
// Flash attention: block = (q-tile of 64 rows) x (batch*head).
// ---------------------------------------------------------------------------
#define SWZ(d) (((d) >> 2) & 15)

__global__ __launch_bounds__(256) void attn_kernel(
    const float* __restrict__ qkv, float* __restrict__ att)
{
    extern __shared__ float sm[];
    float* Qt  = sm;            // [64 d][64 r] swizzled
    float* Kt  = sm + 4096;     // [64 d][64 c] swizzled
    float* Vs  = sm + 8192;     // [64 c][64 d] natural
    float* Ps  = sm + 12288;    // [64 r][68]   probs
    float* m_s = sm + 12288 + 64 * 68;
    float* l_s = m_s + 64;
    float* a_s = l_s + 64;

    const int tid = threadIdx.x;
    const int tx = tid & 15;
    const int ty = tid >> 4;
    const int qt = blockIdx.x;
    const int b  = blockIdx.y >> 4;
    const int h  = blockIdx.y & 15;
    const int len = g_len[b];

    const float* qb = qkv + (size_t)b * TT * H3 + h * HD;
    const float* kb = qb + HH;
    const float* vb = qb + 2 * HH;

    // Load Q tile transposed+swizzled
    {
        const int rr = tid >> 4;
        const int d0 = (tid & 15) * 4;
        #pragma unroll
        for (int it = 0; it < 4; it++) {
            int r = rr + it * 16;
            float4 q4 = *(const float4*)(qb + (size_t)(qt * 64 + r) * H3 + d0);
            const float* qv = (const float*)&q4;
            #pragma unroll
            for (int x = 0; x < 4; x++) {
                int d = d0 + x;
                Qt[d * 64 + ((((r >> 2) ^ SWZ(d)) << 2) | (r & 3))] = qv[x];
            }
        }
    }
    if (tid < 64) { m_s[tid] = -1e30f; l_s[tid] = 0.f; }

    float o[4][4];
    #pragma unroll
    for (int i = 0; i < 4; i++)
        #pragma unroll
        for (int j = 0; j < 4; j++) o[i][j] = 0.f;
    __syncthreads();

    const int kt_max = min(qt, (len - 1) >> 6);
    for (int kt = 0; kt <= kt_max; kt++) {
        {
            const int rr = tid >> 4;
            const int d0 = (tid & 15) * 4;
            #pragma unroll
            for (int it = 0; it < 4; it++) {
                int c = rr + it * 16;
                float4 k4 = *(const float4*)(kb + (size_t)(kt * 64 + c) * H3 + d0);
                const float* kv = (const float*)&k4;
                #pragma unroll
                for (int x = 0; x < 4; x++) {
                    int d = d0 + x;
                    Kt[d * 64 + ((((c >> 2) ^ SWZ(d)) << 2) | (c & 3))] = kv[x];
                }
                float4 v4 = *(const float4*)(vb + (size_t)(kt * 64 + c) * H3 + d0);
                *(float4*)&Vs[c * 64 + d0] = v4;
            }
        }
        __syncthreads();

        // S = Q @ K^T
        float s[4][4];
        #pragma unroll
        for (int i = 0; i < 4; i++)
            #pragma unroll
            for (int j = 0; j < 4; j++) s[i][j] = 0.f;

        #pragma unroll 8
        for (int d = 0; d < 64; d++) {
            const int sw = SWZ(d);
            float4 qa = *(const float4*)&Qt[d * 64 + ((ty ^ sw) << 2)];
            float4 ka = *(const float4*)&Kt[d * 64 + ((tx ^ sw) << 2)];
            const float* qv = (const float*)&qa;
            const float* kv = (const float*)&ka;
            #pragma unroll
            for (int i = 0; i < 4; i++)
                #pragma unroll
                for (int j = 0; j < 4; j++)
                    s[i][j] += qv[i] * kv[j];
        }

        {
            const int q0 = qt * 64 + ty * 4;
            const int c0 = kt * 64 + tx * 4;
            #pragma unroll
            for (int i = 0; i < 4; i++)
                #pragma unroll
                for (int j = 0; j < 4; j++) {
                    int kc = c0 + j;
                    bool ok = (kc <= q0 + i) && (kc < len);
                    Ps[(ty * 4 + i) * 68 + tx * 4 + j] = ok ? s[i][j] * 0.125f
                                                            : -1e30f;
                }
        }
        __syncthreads();

        // online softmax: 4 lanes per row
        {
            const int r = tid >> 2, qq = tid & 3;
            float* prow = Ps + r * 68 + qq * 16;
            float mx = -1e30f;
            #pragma unroll
            for (int c = 0; c < 16; c++) mx = fmaxf(mx, prow[c]);
            mx = fmaxf(mx, __shfl_xor_sync(0xffffffffu, mx, 1));
            mx = fmaxf(mx, __shfl_xor_sync(0xffffffffu, mx, 2));
            const float mo = m_s[r];
            const float mn = fmaxf(mo, mx);
            float sum = 0.f;
            #pragma unroll
            for (int c = 0; c < 16; c++) {
                float e = __expf(prow[c] - mn);
                prow[c] = e;
                sum += e;
            }
            sum += __shfl_xor_sync(0xffffffffu, sum, 1);
            sum += __shfl_xor_sync(0xffffffffu, sum, 2);
            if (qq == 0) {
                float a = __expf(mo - mn);
                a_s[r] = a;
                l_s[r] = l_s[r] * a + sum;
                m_s[r] = mn;
            }
        }
        __syncthreads();

        // rescale O, then O += P @ V
        #pragma unroll
        for (int i = 0; i < 4; i++) {
            float a = a_s[ty * 4 + i];
            #pragma unroll
            for (int j = 0; j < 4; j++) o[i][j] *= a;
        }
        #pragma unroll 4
        for (int c = 0; c < 64; c++) {
            float4 v4 = *(const float4*)&Vs[c * 64 + tx * 4];
            const float* vv = (const float*)&v4;
            #pragma unroll
            for (int i = 0; i < 4; i++) {
                float p = Ps[(ty * 4 + i) * 68 + c];
                #pragma unroll
                for (int j = 0; j < 4; j++) o[i][j] += p * vv[j];
            }
        }
        __syncthreads();
    }

    #pragma unroll
    for (int i = 0; i < 4; i++) {
        const int r = ty * 4 + i;
        const float inv = 1.f / l_s[r];
        float4 res = {o[i][0] * inv, o[i][1] * inv, o[i][2] * inv, o[i][3] * inv};
        *(float4*)&att[(size_t)b * TT * HH + (size_t)(qt * 64 + r) * HH
                       + h * HD + tx * 4] = res;
    }
}

// ---------------------------------------------------------------------------

static const int ATTN_SMEM = (4096 * 3 + 64 * 68 + 3 * 64) * 4;  // 67328 B

extern "C" void kernel_launch(void* const* d_in, const int* in_sizes, int n_in,
                              void* d_out, int out_size)
{
    const float*         inp   = (const float*)d_in[0];
    const unsigned char* mask  = (const unsigned char*)d_in[1];
    const float*         w_qkv = (const float*)d_in[2];
    const float*         b_qkv = (const float*)d_in[3];
    const float*         w_out = (const float*)d_in[4];
    const float*         b_out = (const float*)d_in[5];
    float*               out   = (float*)d_out;

    float *qkv_p, *att_p;
    cudaGetSymbolAddress((void**)&qkv_p, g_qkv);
    cudaGetSymbolAddress((void**)&att_p, g_att);
    cudaFuncSetAttribute(attn_kernel,
                         cudaFuncAttributeMaxDynamicSharedMemorySize, ATTN_SMEM);

    len_kernel<<<BB, 256>>>(mask);
    sgemm_bias<<<dim3(H3 / 128, (BB * TT) / 128), 256>>>(
        inp, w_qkv, b_qkv, qkv_p, BB * TT, H3, HH);
    attn_kernel<<<dim3(TT / 64, BB * NH), 256, ATTN_SMEM>>>(qkv_p, att_p);
    sgemm_bias<<<dim3(HH / 128, (BB * TT) / 128), 256>>>(
        att_p, w_out, b_out, out, BB * TT, HH, HH);
}

// round 3
// speedup vs baseline: 1.6047x; 1.6047x over previous
#include <cuda_runtime.h>
#include <math.h>

#define BB 4
#define TT 2048
#define HH 1024
#define NH 16
#define HD 64
#define H3 3072

// Scratch (allocation-free rule: __device__ globals)
__device__ float g_qkv[(size_t)BB * TT * H3];   // (B,T,3H)
__device__ float g_att[(size_t)BB * TT * HH];   // (B,T,H)
__device__ int   g_len[BB];

// ---------------------------------------------------------------------------
// Per-batch valid-prefix length; mask dtype sniffed from first 4 bytes.
// ---------------------------------------------------------------------------
__global__ void len_kernel(const unsigned char* __restrict__ mask) {
    __shared__ int sred[256];
    const unsigned int w0 = *(const unsigned int*)mask;
    const int b = blockIdx.x;
    int cnt = 0;
    if (w0 == 0x01010101u) {            // uint8
        for (int t = threadIdx.x; t < TT; t += 256)
            cnt += (mask[(size_t)b * TT + t] != 0) ? 1 : 0;
    } else if (w0 == 0x3F800000u) {     // float32
        const float* m = (const float*)mask;
        for (int t = threadIdx.x; t < TT; t += 256)
            cnt += (m[(size_t)b * TT + t] != 0.f) ? 1 : 0;
    } else {                            // int32
        const int* m = (const int*)mask;
        for (int t = threadIdx.x; t < TT; t += 256)
            cnt += (m[(size_t)b * TT + t] != 0) ? 1 : 0;
    }
    sred[threadIdx.x] = cnt;
    __syncthreads();
    for (int s = 128; s > 0; s >>= 1) {
        if (threadIdx.x < s) sred[threadIdx.x] += sred[threadIdx.x + s];
        __syncthreads();
    }
    if (threadIdx.x == 0) g_len[b] = sred[0];
}

// ---------------------------------------------------------------------------
// TF32 tensor-core GEMM: C(M,N) = A(M,K) @ W(K,N) + bias(N)
// 128x128 tile, K-chunk 16, 8 warps, warp tile 64(M)x32(N), mma.m16n8k8.
// ---------------------------------------------------------------------------
__device__ __forceinline__ unsigned f2tf32(float f) {
    unsigned u;
    asm("cvt.rna.tf32.f32 %0, %1;" : "=r"(u) : "f"(f));
    return u;
}

__device__ __forceinline__ void mma_tf32(
    float* d, const unsigned* a, const unsigned* b)
{
    asm volatile(
        "mma.sync.aligned.m16n8k8.row.col.f32.tf32.tf32.f32 "
        "{%0,%1,%2,%3}, {%4,%5,%6,%7}, {%8,%9}, {%0,%1,%2,%3};\n"
        : "+f"(d[0]), "+f"(d[1]), "+f"(d[2]), "+f"(d[3])
        : "r"(a[0]), "r"(a[1]), "r"(a[2]), "r"(a[3]),
          "r"(b[0]), "r"(b[1]));
}

__global__ __launch_bounds__(256) void tgemm_bias(
    const float* __restrict__ A, const float* __restrict__ W,
    const float* __restrict__ bias, float* __restrict__ C,
    int M, int N, int K)
{
    __shared__ unsigned As[128][20];   // [m][k] tf32 bits, pad 4
    __shared__ unsigned Bs[16][132];   // [k][n] tf32 bits, pad 4

    const int tid   = threadIdx.x;
    const int warp  = tid >> 5;
    const int lane  = tid & 31;
    const int g     = lane >> 2;       // group (0..7)
    const int t     = lane & 3;        // thread-in-group (0..3)
    const int warpM = warp & 1;        // 0..1 -> 64 rows each
    const int warpN = warp >> 1;       // 0..3 -> 32 cols each
    const int brow  = blockIdx.y * 128;
    const int bcol  = blockIdx.x * 128;

    // A loader: rows ar, ar+64; cols ac..ac+3 of the 16-wide chunk
    const int ar = tid >> 2;           // 0..63
    const int ac = (tid & 3) * 4;      // 0,4,8,12
    // B loader: k-rows br, br+8; cols bc..bc+3 of 128
    const int br = tid >> 5;           // 0..7
    const int bc = (tid & 31) * 4;

    const float* Ap = A + (size_t)(brow + ar) * K + ac;
    const float* Bp = W + (size_t)br * N + bcol + bc;

    float acc[4][4][4];
    #pragma unroll
    for (int i = 0; i < 4; i++)
        #pragma unroll
        for (int j = 0; j < 4; j++)
            #pragma unroll
            for (int q = 0; q < 4; q++) acc[i][j][q] = 0.f;

    // prologue: load chunk 0 into registers
    float4 a0b = *(const float4*)(Ap);
    float4 a1b = *(const float4*)(Ap + (size_t)64 * K);
    float4 b0b = *(const float4*)(Bp);
    float4 b1b = *(const float4*)(Bp + (size_t)8 * N);

    const int nchunks = K >> 4;
    for (int kc = 0; kc < nchunks; kc++) {
        // store current chunk to smem (cvt to tf32)
        As[ar][ac + 0]      = f2tf32(a0b.x);
        As[ar][ac + 1]      = f2tf32(a0b.y);
        As[ar][ac + 2]      = f2tf32(a0b.z);
        As[ar][ac + 3]      = f2tf32(a0b.w);
        As[ar + 64][ac + 0] = f2tf32(a1b.x);
        As[ar + 64][ac + 1] = f2tf32(a1b.y);
        As[ar + 64][ac + 2] = f2tf32(a1b.z);
        As[ar + 64][ac + 3] = f2tf32(a1b.w);
        Bs[br][bc + 0]      = f2tf32(b0b.x);
        Bs[br][bc + 1]      = f2tf32(b0b.y);
        Bs[br][bc + 2]      = f2tf32(b0b.z);
        Bs[br][bc + 3]      = f2tf32(b0b.w);
        Bs[br + 8][bc + 0]  = f2tf32(b1b.x);
        Bs[br + 8][bc + 1]  = f2tf32(b1b.y);
        Bs[br + 8][bc + 2]  = f2tf32(b1b.z);
        Bs[br + 8][bc + 3]  = f2tf32(b1b.w);
        __syncthreads();

        // prefetch next chunk (LDG in flight during the MMAs below)
        if (kc + 1 < nchunks) {
            const float* Ap2 = Ap + (kc + 1) * 16;
            const float* Bp2 = Bp + (size_t)(kc + 1) * 16 * N;
            a0b = *(const float4*)(Ap2);
            a1b = *(const float4*)(Ap2 + (size_t)64 * K);
            b0b = *(const float4*)(Bp2);
            b1b = *(const float4*)(Bp2 + (size_t)8 * N);
        }

        #pragma unroll
        for (int ks = 0; ks < 2; ks++) {
            const int k0 = ks * 8;
            unsigned af[4][4];
            #pragma unroll
            for (int mt = 0; mt < 4; mt++) {
                const int r = warpM * 64 + mt * 16;
                af[mt][0] = As[r + g][k0 + t];
                af[mt][1] = As[r + g + 8][k0 + t];
                af[mt][2] = As[r + g][k0 + t + 4];
                af[mt][3] = As[r + g + 8][k0 + t + 4];
            }
            unsigned bf[4][2];
            #pragma unroll
            for (int nt = 0; nt < 4; nt++) {
                const int c = warpN * 32 + nt * 8 + g;
                bf[nt][0] = Bs[k0 + t][c];
                bf[nt][1] = Bs[k0 + t + 4][c];
            }
            #pragma unroll
            for (int mt = 0; mt < 4; mt++)
                #pragma unroll
                for (int nt = 0; nt < 4; nt++)
                    mma_tf32(acc[mt][nt], af[mt], bf[nt]);
        }
        __syncthreads();
    }

    // epilogue: bias + store
    #pragma unroll
    for (int mt = 0; mt < 4; mt++) {
        const int r0 = brow + warpM * 64 + mt * 16 + g;
        #pragma unroll
        for (int nt = 0; nt < 4; nt++) {
            const int c = bcol + warpN * 32 + nt * 8 + 2 * t;
            const float bv0 = bias[c], bv1 = bias[c + 1];
            float2 v0 = {acc[mt][nt][0] + bv0, acc[mt][nt][1] + bv1};
            float2 v1 = {acc[mt][nt][2] + bv0, acc[mt][nt][3] + bv1};
            *(float2*)&C[(size_t)r0 * N + c]       = v0;
            *(float2*)&C[(size_t)(r0 + 8) * N + c] = v1;
        }
    }
}

// ---------------------------------------------------------------------------
// Flash attention (fp32), block = (q-tile of 64 rows) x (batch*head).
// ---------------------------------------------------------------------------
#define SWZ(d) (((d) >> 2) & 15)

__global__ __launch_bounds__(256) void attn_kernel(
    const float* __restrict__ qkv, float* __restrict__ att)
{
    extern __shared__ float sm[];
    float* Qt  = sm;            // [64 d][64 r] swizzled
    float* Kt  = sm + 4096;     // [64 d][64 c] swizzled
    float* Vs  = sm + 8192;     // [64 c][64 d] natural
    float* Ps  = sm + 12288;    // [64 r][68]   probs
    float* m_s = sm + 12288 + 64 * 68;
    float* l_s = m_s + 64;
    float* a_s = l_s + 64;

    const int tid = threadIdx.x;
    const int tx = tid & 15;
    const int ty = tid >> 4;
    const int qt = blockIdx.x;
    const int b  = blockIdx.y >> 4;
    const int h  = blockIdx.y & 15;
    const int len = g_len[b];

    const float* qb = qkv + (size_t)b * TT * H3 + h * HD;
    const float* kb = qb + HH;
    const float* vb = qb + 2 * HH;

    {
        const int rr = tid >> 4;
        const int d0 = (tid & 15) * 4;
        #pragma unroll
        for (int it = 0; it < 4; it++) {
            int r = rr + it * 16;
            float4 q4 = *(const float4*)(qb + (size_t)(qt * 64 + r) * H3 + d0);
            const float* qv = (const float*)&q4;
            #pragma unroll
            for (int x = 0; x < 4; x++) {
                int d = d0 + x;
                Qt[d * 64 + ((((r >> 2) ^ SWZ(d)) << 2) | (r & 3))] = qv[x];
            }
        }
    }
    if (tid < 64) { m_s[tid] = -1e30f; l_s[tid] = 0.f; }

    float o[4][4];
    #pragma unroll
    for (int i = 0; i < 4; i++)
        #pragma unroll
        for (int j = 0; j < 4; j++) o[i][j] = 0.f;
    __syncthreads();

    const int kt_max = min(qt, (len - 1) >> 6);
    for (int kt = 0; kt <= kt_max; kt++) {
        {
            const int rr = tid >> 4;
            const int d0 = (tid & 15) * 4;
            #pragma unroll
            for (int it = 0; it < 4; it++) {
                int c = rr + it * 16;
                float4 k4 = *(const float4*)(kb + (size_t)(kt * 64 + c) * H3 + d0);
                const float* kv = (const float*)&k4;
                #pragma unroll
                for (int x = 0; x < 4; x++) {
                    int d = d0 + x;
                    Kt[d * 64 + ((((c >> 2) ^ SWZ(d)) << 2) | (c & 3))] = kv[x];
                }
                float4 v4 = *(const float4*)(vb + (size_t)(kt * 64 + c) * H3 + d0);
                *(float4*)&Vs[c * 64 + d0] = v4;
            }
        }
        __syncthreads();

        float s[4][4];
        #pragma unroll
        for (int i = 0; i < 4; i++)
            #pragma unroll
            for (int j = 0; j < 4; j++) s[i][j] = 0.f;

        #pragma unroll 8
        for (int d = 0; d < 64; d++) {
            const int sw = SWZ(d);
            float4 qa = *(const float4*)&Qt[d * 64 + ((ty ^ sw) << 2)];
            float4 ka = *(const float4*)&Kt[d * 64 + ((tx ^ sw) << 2)];
            const float* qv = (const float*)&qa;
            const float* kv = (const float*)&ka;
            #pragma unroll
            for (int i = 0; i < 4; i++)
                #pragma unroll
                for (int j = 0; j < 4; j++)
                    s[i][j] += qv[i] * kv[j];
        }

        {
            const int q0 = qt * 64 + ty * 4;
            const int c0 = kt * 64 + tx * 4;
            #pragma unroll
            for (int i = 0; i < 4; i++)
                #pragma unroll
                for (int j = 0; j < 4; j++) {
                    int kc = c0 + j;
                    bool ok = (kc <= q0 + i) && (kc < len);
                    Ps[(ty * 4 + i) * 68 + tx * 4 + j] = ok ? s[i][j] * 0.125f
                                                            : -1e30f;
                }
        }
        __syncthreads();

        {
            const int r = tid >> 2, qq = tid & 3;
            float* prow = Ps + r * 68 + qq * 16;
            float mx = -1e30f;
            #pragma unroll
            for (int c = 0; c < 16; c++) mx = fmaxf(mx, prow[c]);
            mx = fmaxf(mx, __shfl_xor_sync(0xffffffffu, mx, 1));
            mx = fmaxf(mx, __shfl_xor_sync(0xffffffffu, mx, 2));
            const float mo = m_s[r];
            const float mn = fmaxf(mo, mx);
            float sum = 0.f;
            #pragma unroll
            for (int c = 0; c < 16; c++) {
                float e = __expf(prow[c] - mn);
                prow[c] = e;
                sum += e;
            }
            sum += __shfl_xor_sync(0xffffffffu, sum, 1);
            sum += __shfl_xor_sync(0xffffffffu, sum, 2);
            if (qq == 0) {
                float a = __expf(mo - mn);
                a_s[r] = a;
                l_s[r] = l_s[r] * a + sum;
                m_s[r] = mn;
            }
        }
        __syncthreads();

        #pragma unroll
        for (int i = 0; i < 4; i++) {
            float a = a_s[ty * 4 + i];
            #pragma unroll
            for (int j = 0; j < 4; j++) o[i][j] *= a;
        }
        #pragma unroll 4
        for (int c = 0; c < 64; c++) {
            float4 v4 = *(const float4*)&Vs[c * 64 + tx * 4];
            const float* vv = (const float*)&v4;
            #pragma unroll
            for (int i = 0; i < 4; i++) {
                float p = Ps[(ty * 4 + i) * 68 + c];
                #pragma unroll
                for (int j = 0; j < 4; j++) o[i][j] += p * vv[j];
            }
        }
        __syncthreads();
    }

    #pragma unroll
    for (int i = 0; i < 4; i++) {
        const int r = ty * 4 + i;
        const float inv = 1.f / l_s[r];
        float4 res = {o[i][0] * inv, o[i][1] * inv, o[i][2] * inv, o[i][3] * inv};
        *(float4*)&att[(size_t)b * TT * HH + (size_t)(qt * 64 + r) * HH
                       + h * HD + tx * 4] = res;
    }
}

// ---------------------------------------------------------------------------

static const int ATTN_SMEM = (4096 * 3 + 64 * 68 + 3 * 64) * 4;  // 67328 B

extern "C" void kernel_launch(void* const* d_in, const int* in_sizes, int n_in,
                              void* d_out, int out_size)
{
    const float*         inp   = (const float*)d_in[0];
    const unsigned char* mask  = (const unsigned char*)d_in[1];
    const float*         w_qkv = (const float*)d_in[2];
    const float*         b_qkv = (const float*)d_in[3];
    const float*         w_out = (const float*)d_in[4];
    const float*         b_out = (const float*)d_in[5];
    float*               out   = (float*)d_out;

    float *qkv_p, *att_p;
    cudaGetSymbolAddress((void**)&qkv_p, g_qkv);
    cudaGetSymbolAddress((void**)&att_p, g_att);
    cudaFuncSetAttribute(attn_kernel,
                         cudaFuncAttributeMaxDynamicSharedMemorySize, ATTN_SMEM);

    len_kernel<<<BB, 256>>>(mask);
    tgemm_bias<<<dim3(H3 / 128, (BB * TT) / 128), 256>>>(
        inp, w_qkv, b_qkv, qkv_p, BB * TT, H3, HH);
    attn_kernel<<<dim3(TT / 64, BB * NH), 256, ATTN_SMEM>>>(qkv_p, att_p);
    tgemm_bias<<<dim3(HH / 128, (BB * TT) / 128), 256>>>(
        att_p, w_out, b_out, out, BB * TT, HH, HH);
}

// round 4
// speedup vs baseline: 2.3698x; 1.4768x over previous
#include <cuda_runtime.h>
#include <math.h>

#define BB 4
#define TT 2048
#define HH 1024
#define NH 16
#define HD 64
#define H3 3072

// Scratch (allocation-free rule: __device__ globals)
__device__ float g_qkv[(size_t)BB * TT * H3];   // (B,T,3H)
__device__ float g_att[(size_t)BB * TT * HH];   // (B,T,H)
__device__ int   g_len[BB];

// ---------------------------------------------------------------------------
// Per-batch valid-prefix length; mask dtype sniffed from first 4 bytes.
// ---------------------------------------------------------------------------
__global__ void len_kernel(const unsigned char* __restrict__ mask) {
    __shared__ int sred[256];
    const unsigned int w0 = *(const unsigned int*)mask;
    const int b = blockIdx.x;
    int cnt = 0;
    if (w0 == 0x01010101u) {            // uint8
        for (int t = threadIdx.x; t < TT; t += 256)
            cnt += (mask[(size_t)b * TT + t] != 0) ? 1 : 0;
    } else if (w0 == 0x3F800000u) {     // float32
        const float* m = (const float*)mask;
        for (int t = threadIdx.x; t < TT; t += 256)
            cnt += (m[(size_t)b * TT + t] != 0.f) ? 1 : 0;
    } else {                            // int32
        const int* m = (const int*)mask;
        for (int t = threadIdx.x; t < TT; t += 256)
            cnt += (m[(size_t)b * TT + t] != 0) ? 1 : 0;
    }
    sred[threadIdx.x] = cnt;
    __syncthreads();
    for (int s = 128; s > 0; s >>= 1) {
        if (threadIdx.x < s) sred[threadIdx.x] += sred[threadIdx.x + s];
        __syncthreads();
    }
    if (threadIdx.x == 0) g_len[b] = sred[0];
}

// ---------------------------------------------------------------------------
// tf32 helpers (mapping proven correct by R3 tgemm)
// ---------------------------------------------------------------------------
__device__ __forceinline__ unsigned f2tf32(float f) {
    unsigned u;
    asm("cvt.rna.tf32.f32 %0, %1;" : "=r"(u) : "f"(f));
    return u;
}

__device__ __forceinline__ void mma_tf32(
    float* d, const unsigned* a, const unsigned* b)
{
    asm volatile(
        "mma.sync.aligned.m16n8k8.row.col.f32.tf32.tf32.f32 "
        "{%0,%1,%2,%3}, {%4,%5,%6,%7}, {%8,%9}, {%0,%1,%2,%3};\n"
        : "+f"(d[0]), "+f"(d[1]), "+f"(d[2]), "+f"(d[3])
        : "r"(a[0]), "r"(a[1]), "r"(a[2]), "r"(a[3]),
          "r"(b[0]), "r"(b[1]));
}

// ---------------------------------------------------------------------------
// TF32 tensor-core GEMM: C(M,N) = A(M,K) @ W(K,N) + bias(N)
// ---------------------------------------------------------------------------
__global__ __launch_bounds__(256) void tgemm_bias(
    const float* __restrict__ A, const float* __restrict__ W,
    const float* __restrict__ bias, float* __restrict__ C,
    int M, int N, int K)
{
    __shared__ unsigned As[128][20];
    __shared__ unsigned Bs[16][132];

    const int tid   = threadIdx.x;
    const int warp  = tid >> 5;
    const int lane  = tid & 31;
    const int g     = lane >> 2;
    const int t     = lane & 3;
    const int warpM = warp & 1;
    const int warpN = warp >> 1;
    const int brow  = blockIdx.y * 128;
    const int bcol  = blockIdx.x * 128;

    const int ar = tid >> 2;
    const int ac = (tid & 3) * 4;
    const int br = tid >> 5;
    const int bc = (tid & 31) * 4;

    const float* Ap = A + (size_t)(brow + ar) * K + ac;
    const float* Bp = W + (size_t)br * N + bcol + bc;

    float acc[4][4][4];
    #pragma unroll
    for (int i = 0; i < 4; i++)
        #pragma unroll
        for (int j = 0; j < 4; j++)
            #pragma unroll
            for (int q = 0; q < 4; q++) acc[i][j][q] = 0.f;

    float4 a0b = *(const float4*)(Ap);
    float4 a1b = *(const float4*)(Ap + (size_t)64 * K);
    float4 b0b = *(const float4*)(Bp);
    float4 b1b = *(const float4*)(Bp + (size_t)8 * N);

    const int nchunks = K >> 4;
    for (int kc = 0; kc < nchunks; kc++) {
        As[ar][ac + 0]      = f2tf32(a0b.x);
        As[ar][ac + 1]      = f2tf32(a0b.y);
        As[ar][ac + 2]      = f2tf32(a0b.z);
        As[ar][ac + 3]      = f2tf32(a0b.w);
        As[ar + 64][ac + 0] = f2tf32(a1b.x);
        As[ar + 64][ac + 1] = f2tf32(a1b.y);
        As[ar + 64][ac + 2] = f2tf32(a1b.z);
        As[ar + 64][ac + 3] = f2tf32(a1b.w);
        Bs[br][bc + 0]      = f2tf32(b0b.x);
        Bs[br][bc + 1]      = f2tf32(b0b.y);
        Bs[br][bc + 2]      = f2tf32(b0b.z);
        Bs[br][bc + 3]      = f2tf32(b0b.w);
        Bs[br + 8][bc + 0]  = f2tf32(b1b.x);
        Bs[br + 8][bc + 1]  = f2tf32(b1b.y);
        Bs[br + 8][bc + 2]  = f2tf32(b1b.z);
        Bs[br + 8][bc + 3]  = f2tf32(b1b.w);
        __syncthreads();

        if (kc + 1 < nchunks) {
            const float* Ap2 = Ap + (kc + 1) * 16;
            const float* Bp2 = Bp + (size_t)(kc + 1) * 16 * N;
            a0b = *(const float4*)(Ap2);
            a1b = *(const float4*)(Ap2 + (size_t)64 * K);
            b0b = *(const float4*)(Bp2);
            b1b = *(const float4*)(Bp2 + (size_t)8 * N);
        }

        #pragma unroll
        for (int ks = 0; ks < 2; ks++) {
            const int k0 = ks * 8;
            unsigned af[4][4];
            #pragma unroll
            for (int mt = 0; mt < 4; mt++) {
                const int r = warpM * 64 + mt * 16;
                af[mt][0] = As[r + g][k0 + t];
                af[mt][1] = As[r + g + 8][k0 + t];
                af[mt][2] = As[r + g][k0 + t + 4];
                af[mt][3] = As[r + g + 8][k0 + t + 4];
            }
            unsigned bf[4][2];
            #pragma unroll
            for (int nt = 0; nt < 4; nt++) {
                const int c = warpN * 32 + nt * 8 + g;
                bf[nt][0] = Bs[k0 + t][c];
                bf[nt][1] = Bs[k0 + t + 4][c];
            }
            #pragma unroll
            for (int mt = 0; mt < 4; mt++)
                #pragma unroll
                for (int nt = 0; nt < 4; nt++)
                    mma_tf32(acc[mt][nt], af[mt], bf[nt]);
        }
        __syncthreads();
    }

    #pragma unroll
    for (int mt = 0; mt < 4; mt++) {
        const int r0 = brow + warpM * 64 + mt * 16 + g;
        #pragma unroll
        for (int nt = 0; nt < 4; nt++) {
            const int c = bcol + warpN * 32 + nt * 8 + 2 * t;
            const float bv0 = bias[c], bv1 = bias[c + 1];
            float2 v0 = {acc[mt][nt][0] + bv0, acc[mt][nt][1] + bv1};
            float2 v1 = {acc[mt][nt][2] + bv0, acc[mt][nt][3] + bv1};
            *(float2*)&C[(size_t)r0 * N + c]       = v0;
            *(float2*)&C[(size_t)(r0 + 8) * N + c] = v1;
        }
    }
}

// ---------------------------------------------------------------------------
// Flash attention with tf32 MMA for S=QK^T and O+=P@V.
// 8 warps: warp = (wm, wn); wm = warp>>1 -> 16 q-rows, wn = warp&1 -> 32 cols.
// All smem operand arrays stride 68 (conflict-free fragment LDS: 4g+t mod 32).
// ---------------------------------------------------------------------------
__global__ __launch_bounds__(256) void attn_mma(
    const float* __restrict__ qkv, float* __restrict__ att)
{
    extern __shared__ unsigned smu[];
    unsigned* Qs = smu;                         // [64][68] tf32 bits
    unsigned* Ks = smu + 64 * 68;               // [64 c][68 d]
    unsigned* Vs = smu + 2 * 64 * 68;           // [64 k][68 d]
    float*    Ps = (float*)(smu + 3 * 64 * 68); // [64 r][68] scores/probs
    float*    m_s = Ps + 64 * 68;
    float*    l_s = m_s + 64;
    float*    a_s = l_s + 64;

    const int tid  = threadIdx.x;
    const int warp = tid >> 5;
    const int lane = tid & 31;
    const int g = lane >> 2;
    const int t = lane & 3;
    const int wm = warp >> 1;      // 0..3
    const int wn = warp & 1;       // 0..1
    const int qt = blockIdx.x;
    const int b  = blockIdx.y >> 4;
    const int h  = blockIdx.y & 15;
    const int len = g_len[b];

    const float* qb = qkv + (size_t)b * TT * H3 + h * HD;
    const float* kb = qb + HH;
    const float* vb = qb + 2 * HH;

    // Load Q tile (cvt to tf32)
    {
        const int r = tid >> 4, d0 = (tid & 15) * 4;
        #pragma unroll
        for (int it = 0; it < 4; it++) {
            const int rr = r + it * 16;
            float4 q4 = *(const float4*)(qb + (size_t)(qt * 64 + rr) * H3 + d0);
            Qs[rr * 68 + d0 + 0] = f2tf32(q4.x);
            Qs[rr * 68 + d0 + 1] = f2tf32(q4.y);
            Qs[rr * 68 + d0 + 2] = f2tf32(q4.z);
            Qs[rr * 68 + d0 + 3] = f2tf32(q4.w);
        }
    }
    if (tid < 64) { m_s[tid] = -1e30f; l_s[tid] = 0.f; }

    float o[4][4];
    #pragma unroll
    for (int nt = 0; nt < 4; nt++)
        #pragma unroll
        for (int q = 0; q < 4; q++) o[nt][q] = 0.f;
    __syncthreads();

    const int kt_max = min(qt, (len - 1) >> 6);
    for (int kt = 0; kt <= kt_max; kt++) {
        // Load K, V tiles (cvt to tf32)
        {
            const int r = tid >> 4, d0 = (tid & 15) * 4;
            #pragma unroll
            for (int it = 0; it < 4; it++) {
                const int c = r + it * 16;
                float4 k4 = *(const float4*)(kb + (size_t)(kt * 64 + c) * H3 + d0);
                Ks[c * 68 + d0 + 0] = f2tf32(k4.x);
                Ks[c * 68 + d0 + 1] = f2tf32(k4.y);
                Ks[c * 68 + d0 + 2] = f2tf32(k4.z);
                Ks[c * 68 + d0 + 3] = f2tf32(k4.w);
                float4 v4 = *(const float4*)(vb + (size_t)(kt * 64 + c) * H3 + d0);
                Vs[c * 68 + d0 + 0] = f2tf32(v4.x);
                Vs[c * 68 + d0 + 1] = f2tf32(v4.y);
                Vs[c * 68 + d0 + 2] = f2tf32(v4.z);
                Vs[c * 68 + d0 + 3] = f2tf32(v4.w);
            }
        }
        __syncthreads();

        // S = Q @ K^T via MMA  (B[k][n] = K[n][k] -> Ks[c][d])
        float s[4][4];
        #pragma unroll
        for (int nt = 0; nt < 4; nt++)
            #pragma unroll
            for (int q = 0; q < 4; q++) s[nt][q] = 0.f;

        #pragma unroll
        for (int k0 = 0; k0 < 64; k0 += 8) {
            unsigned af[4];
            const int r0 = wm * 16;
            af[0] = Qs[(r0 + g) * 68 + k0 + t];
            af[1] = Qs[(r0 + g + 8) * 68 + k0 + t];
            af[2] = Qs[(r0 + g) * 68 + k0 + t + 4];
            af[3] = Qs[(r0 + g + 8) * 68 + k0 + t + 4];
            #pragma unroll
            for (int nt = 0; nt < 4; nt++) {
                const int c = wn * 32 + nt * 8 + g;
                unsigned bf[2] = { Ks[c * 68 + k0 + t], Ks[c * 68 + k0 + t + 4] };
                mma_tf32(s[nt], af, bf);
            }
        }

        // Scale + mask, stash scores into Ps
        {
            const int r0 = wm * 16 + g;
            const int q0 = qt * 64;
            #pragma unroll
            for (int nt = 0; nt < 4; nt++) {
                const int c0 = wn * 32 + nt * 8 + 2 * t;
                const int kc = kt * 64 + c0;
                Ps[r0 * 68 + c0] =
                    (kc <= q0 + r0 && kc < len) ? s[nt][0] * 0.125f : -1e30f;
                Ps[r0 * 68 + c0 + 1] =
                    (kc + 1 <= q0 + r0 && kc + 1 < len) ? s[nt][1] * 0.125f : -1e30f;
                Ps[(r0 + 8) * 68 + c0] =
                    (kc <= q0 + r0 + 8 && kc < len) ? s[nt][2] * 0.125f : -1e30f;
                Ps[(r0 + 8) * 68 + c0 + 1] =
                    (kc + 1 <= q0 + r0 + 8 && kc + 1 < len) ? s[nt][3] * 0.125f : -1e30f;
            }
        }
        __syncthreads();

        // Online softmax: 4 lanes per row; probs stored pre-rounded to tf32
        {
            const int r = tid >> 2, qq = tid & 3;
            float* prow = Ps + r * 68 + qq * 16;
            float mx = -1e30f;
            #pragma unroll
            for (int c = 0; c < 16; c++) mx = fmaxf(mx, prow[c]);
            mx = fmaxf(mx, __shfl_xor_sync(0xffffffffu, mx, 1));
            mx = fmaxf(mx, __shfl_xor_sync(0xffffffffu, mx, 2));
            const float mo = m_s[r];
            const float mn = fmaxf(mo, mx);
            float sum = 0.f;
            #pragma unroll
            for (int c = 0; c < 16; c++) {
                float e = __expf(prow[c] - mn);
                prow[c] = __uint_as_float(f2tf32(e));
                sum += e;
            }
            sum += __shfl_xor_sync(0xffffffffu, sum, 1);
            sum += __shfl_xor_sync(0xffffffffu, sum, 2);
            if (qq == 0) {
                float a = __expf(mo - mn);
                a_s[r] = a;
                l_s[r] = l_s[r] * a + sum;
                m_s[r] = mn;
            }
        }
        __syncthreads();

        // Rescale O accumulators
        {
            const float a0 = a_s[wm * 16 + g];
            const float a1 = a_s[wm * 16 + g + 8];
            #pragma unroll
            for (int nt = 0; nt < 4; nt++) {
                o[nt][0] *= a0; o[nt][1] *= a0;
                o[nt][2] *= a1; o[nt][3] *= a1;
            }
        }

        // O += P @ V via MMA  (A = Ps tf32 bits, B[k][n] = Vs[k][d])
        {
            const unsigned* Pu = (const unsigned*)Ps;
            #pragma unroll
            for (int k0 = 0; k0 < 64; k0 += 8) {
                unsigned af[4];
                const int r0 = wm * 16;
                af[0] = Pu[(r0 + g) * 68 + k0 + t];
                af[1] = Pu[(r0 + g + 8) * 68 + k0 + t];
                af[2] = Pu[(r0 + g) * 68 + k0 + t + 4];
                af[3] = Pu[(r0 + g + 8) * 68 + k0 + t + 4];
                #pragma unroll
                for (int nt = 0; nt < 4; nt++) {
                    const int c = wn * 32 + nt * 8 + g;
                    unsigned bf[2] = { Vs[(k0 + t) * 68 + c],
                                       Vs[(k0 + t + 4) * 68 + c] };
                    mma_tf32(o[nt], af, bf);
                }
            }
        }
        __syncthreads();
    }

    // Epilogue: normalize rows, write (B,T,H)
    {
        const int r0 = wm * 16 + g;
        const float inv0 = 1.f / l_s[r0];
        const float inv1 = 1.f / l_s[r0 + 8];
        float* ob = att + (size_t)b * TT * HH + (size_t)(qt * 64) * HH + h * HD;
        #pragma unroll
        for (int nt = 0; nt < 4; nt++) {
            const int c = wn * 32 + nt * 8 + 2 * t;
            float2 v0 = { o[nt][0] * inv0, o[nt][1] * inv0 };
            float2 v1 = { o[nt][2] * inv1, o[nt][3] * inv1 };
            *(float2*)&ob[(size_t)r0 * HH + c]       = v0;
            *(float2*)&ob[(size_t)(r0 + 8) * HH + c] = v1;
        }
    }
}

// ---------------------------------------------------------------------------

static const int ATTN_SMEM = (4 * 64 * 68 + 3 * 64) * 4;  // 70400 B

extern "C" void kernel_launch(void* const* d_in, const int* in_sizes, int n_in,
                              void* d_out, int out_size)
{
    const float*         inp   = (const float*)d_in[0];
    const unsigned char* mask  = (const unsigned char*)d_in[1];
    const float*         w_qkv = (const float*)d_in[2];
    const float*         b_qkv = (const float*)d_in[3];
    const float*         w_out = (const float*)d_in[4];
    const float*         b_out = (const float*)d_in[5];
    float*               out   = (float*)d_out;

    float *qkv_p, *att_p;
    cudaGetSymbolAddress((void**)&qkv_p, g_qkv);
    cudaGetSymbolAddress((void**)&att_p, g_att);
    cudaFuncSetAttribute(attn_mma,
                         cudaFuncAttributeMaxDynamicSharedMemorySize, ATTN_SMEM);

    len_kernel<<<BB, 256>>>(mask);
    tgemm_bias<<<dim3(H3 / 128, (BB * TT) / 128), 256>>>(
        inp, w_qkv, b_qkv, qkv_p, BB * TT, H3, HH);
    attn_mma<<<dim3(TT / 64, BB * NH), 256, ATTN_SMEM>>>(qkv_p, att_p);
    tgemm_bias<<<dim3(HH / 128, (BB * TT) / 128), 256>>>(
        att_p, w_out, b_out, out, BB * TT, HH, HH);
}

// round 5
// speedup vs baseline: 2.4024x; 1.0137x over previous
#include <cuda_runtime.h>
#include <math.h>

#define BB 4
#define TT 2048
#define HH 1024
#define NH 16
#define HD 64
#define H3 3072

// Scratch (allocation-free rule: __device__ globals)
__device__ float g_qkv[(size_t)BB * TT * H3];   // (B,T,3H)
__device__ float g_att[(size_t)BB * TT * HH];   // (B,T,H)
__device__ int   g_len[BB];

// ---------------------------------------------------------------------------
// Per-batch valid-prefix length; mask dtype sniffed from first 4 bytes.
// ---------------------------------------------------------------------------
__global__ void len_kernel(const unsigned char* __restrict__ mask) {
    __shared__ int sred[256];
    const unsigned int w0 = *(const unsigned int*)mask;
    const int b = blockIdx.x;
    int cnt = 0;
    if (w0 == 0x01010101u) {            // uint8
        for (int t = threadIdx.x; t < TT; t += 256)
            cnt += (mask[(size_t)b * TT + t] != 0) ? 1 : 0;
    } else if (w0 == 0x3F800000u) {     // float32
        const float* m = (const float*)mask;
        for (int t = threadIdx.x; t < TT; t += 256)
            cnt += (m[(size_t)b * TT + t] != 0.f) ? 1 : 0;
    } else {                            // int32
        const int* m = (const int*)mask;
        for (int t = threadIdx.x; t < TT; t += 256)
            cnt += (m[(size_t)b * TT + t] != 0) ? 1 : 0;
    }
    sred[threadIdx.x] = cnt;
    __syncthreads();
    for (int s = 128; s > 0; s >>= 1) {
        if (threadIdx.x < s) sred[threadIdx.x] += sred[threadIdx.x + s];
        __syncthreads();
    }
    if (threadIdx.x == 0) g_len[b] = sred[0];
}

// ---------------------------------------------------------------------------
// tf32 helpers
// ---------------------------------------------------------------------------
__device__ __forceinline__ unsigned f2tf32(float f) {
    unsigned u;
    asm("cvt.rna.tf32.f32 %0, %1;" : "=r"(u) : "f"(f));
    return u;
}

__device__ __forceinline__ void mma_tf32(
    float* d, const unsigned* a, const unsigned* b)
{
    asm volatile(
        "mma.sync.aligned.m16n8k8.row.col.f32.tf32.tf32.f32 "
        "{%0,%1,%2,%3}, {%4,%5,%6,%7}, {%8,%9}, {%0,%1,%2,%3};\n"
        : "+f"(d[0]), "+f"(d[1]), "+f"(d[2]), "+f"(d[3])
        : "r"(a[0]), "r"(a[1]), "r"(a[2]), "r"(a[3]),
          "r"(b[0]), "r"(b[1]));
}

// ---------------------------------------------------------------------------
// TF32 tensor-core GEMM, double-buffered smem: 1 sync per 16-wide K-chunk.
// C(M,N) = A(M,K) @ W(K,N) + bias(N). 128x128 tile, 8 warps, 64x32 warp tile.
// ---------------------------------------------------------------------------
__global__ __launch_bounds__(256) void tgemm_bias(
    const float* __restrict__ A, const float* __restrict__ W,
    const float* __restrict__ bias, float* __restrict__ C,
    int M, int N, int K)
{
    __shared__ unsigned As[2][128][20];
    __shared__ unsigned Bs[2][16][132];

    const int tid   = threadIdx.x;
    const int warp  = tid >> 5;
    const int lane  = tid & 31;
    const int g     = lane >> 2;
    const int t     = lane & 3;
    const int warpM = warp & 1;
    const int warpN = warp >> 1;
    const int brow  = blockIdx.y * 128;
    const int bcol  = blockIdx.x * 128;

    const int ar = tid >> 2;
    const int ac = (tid & 3) * 4;
    const int br = tid >> 5;
    const int bc = (tid & 31) * 4;

    const float* Ap = A + (size_t)(brow + ar) * K + ac;
    const float* Bp = W + (size_t)br * N + bcol + bc;

    float acc[4][4][4];
    #pragma unroll
    for (int i = 0; i < 4; i++)
        #pragma unroll
        for (int j = 0; j < 4; j++)
            #pragma unroll
            for (int q = 0; q < 4; q++) acc[i][j][q] = 0.f;

    // prologue: chunk 0 -> regs -> stage 0
    float4 a0b = *(const float4*)(Ap);
    float4 a1b = *(const float4*)(Ap + (size_t)64 * K);
    float4 b0b = *(const float4*)(Bp);
    float4 b1b = *(const float4*)(Bp + (size_t)8 * N);

    As[0][ar][ac + 0]      = f2tf32(a0b.x);
    As[0][ar][ac + 1]      = f2tf32(a0b.y);
    As[0][ar][ac + 2]      = f2tf32(a0b.z);
    As[0][ar][ac + 3]      = f2tf32(a0b.w);
    As[0][ar + 64][ac + 0] = f2tf32(a1b.x);
    As[0][ar + 64][ac + 1] = f2tf32(a1b.y);
    As[0][ar + 64][ac + 2] = f2tf32(a1b.z);
    As[0][ar + 64][ac + 3] = f2tf32(a1b.w);
    Bs[0][br][bc + 0]      = f2tf32(b0b.x);
    Bs[0][br][bc + 1]      = f2tf32(b0b.y);
    Bs[0][br][bc + 2]      = f2tf32(b0b.z);
    Bs[0][br][bc + 3]      = f2tf32(b0b.w);
    Bs[0][br + 8][bc + 0]  = f2tf32(b1b.x);
    Bs[0][br + 8][bc + 1]  = f2tf32(b1b.y);
    Bs[0][br + 8][bc + 2]  = f2tf32(b1b.z);
    Bs[0][br + 8][bc + 3]  = f2tf32(b1b.w);
    __syncthreads();

    const int nchunks = K >> 4;
    for (int kc = 0; kc < nchunks; kc++) {
        const int st = kc & 1;

        // prefetch next chunk (LDG in flight during MMAs)
        if (kc + 1 < nchunks) {
            const float* Ap2 = Ap + (kc + 1) * 16;
            const float* Bp2 = Bp + (size_t)(kc + 1) * 16 * N;
            a0b = *(const float4*)(Ap2);
            a1b = *(const float4*)(Ap2 + (size_t)64 * K);
            b0b = *(const float4*)(Bp2);
            b1b = *(const float4*)(Bp2 + (size_t)8 * N);
        }

        #pragma unroll
        for (int ks = 0; ks < 2; ks++) {
            const int k0 = ks * 8;
            unsigned af[4][4];
            #pragma unroll
            for (int mt = 0; mt < 4; mt++) {
                const int r = warpM * 64 + mt * 16;
                af[mt][0] = As[st][r + g][k0 + t];
                af[mt][1] = As[st][r + g + 8][k0 + t];
                af[mt][2] = As[st][r + g][k0 + t + 4];
                af[mt][3] = As[st][r + g + 8][k0 + t + 4];
            }
            unsigned bf[4][2];
            #pragma unroll
            for (int nt = 0; nt < 4; nt++) {
                const int c = warpN * 32 + nt * 8 + g;
                bf[nt][0] = Bs[st][k0 + t][c];
                bf[nt][1] = Bs[st][k0 + t + 4][c];
            }
            #pragma unroll
            for (int mt = 0; mt < 4; mt++)
                #pragma unroll
                for (int nt = 0; nt < 4; nt++)
                    mma_tf32(acc[mt][nt], af[mt], bf[nt]);
        }

        // store next chunk to the other stage (no WAR: other buffer;
        // prior reads of it finished at the sync ending iteration kc-1)
        if (kc + 1 < nchunks) {
            const int sn = st ^ 1;
            As[sn][ar][ac + 0]      = f2tf32(a0b.x);
            As[sn][ar][ac + 1]      = f2tf32(a0b.y);
            As[sn][ar][ac + 2]      = f2tf32(a0b.z);
            As[sn][ar][ac + 3]      = f2tf32(a0b.w);
            As[sn][ar + 64][ac + 0] = f2tf32(a1b.x);
            As[sn][ar + 64][ac + 1] = f2tf32(a1b.y);
            As[sn][ar + 64][ac + 2] = f2tf32(a1b.z);
            As[sn][ar + 64][ac + 3] = f2tf32(a1b.w);
            Bs[sn][br][bc + 0]      = f2tf32(b0b.x);
            Bs[sn][br][bc + 1]      = f2tf32(b0b.y);
            Bs[sn][br][bc + 2]      = f2tf32(b0b.z);
            Bs[sn][br][bc + 3]      = f2tf32(b0b.w);
            Bs[sn][br + 8][bc + 0]  = f2tf32(b1b.x);
            Bs[sn][br + 8][bc + 1]  = f2tf32(b1b.y);
            Bs[sn][br + 8][bc + 2]  = f2tf32(b1b.z);
            Bs[sn][br + 8][bc + 3]  = f2tf32(b1b.w);
            __syncthreads();
        }
    }

    #pragma unroll
    for (int mt = 0; mt < 4; mt++) {
        const int r0 = brow + warpM * 64 + mt * 16 + g;
        #pragma unroll
        for (int nt = 0; nt < 4; nt++) {
            const int c = bcol + warpN * 32 + nt * 8 + 2 * t;
            const float bv0 = bias[c], bv1 = bias[c + 1];
            float2 v0 = {acc[mt][nt][0] + bv0, acc[mt][nt][1] + bv1};
            float2 v1 = {acc[mt][nt][2] + bv0, acc[mt][nt][3] + bv1};
            *(float2*)&C[(size_t)r0 * N + c]       = v0;
            *(float2*)&C[(size_t)(r0 + 8) * N + c] = v1;
        }
    }
}

// ---------------------------------------------------------------------------
// Flash attention with tf32 MMA; K/V tiles register-prefetched one kt ahead.
// ---------------------------------------------------------------------------
__global__ __launch_bounds__(256) void attn_mma(
    const float* __restrict__ qkv, float* __restrict__ att)
{
    extern __shared__ unsigned smu[];
    unsigned* Qs = smu;                         // [64][68] tf32 bits
    unsigned* Ks = smu + 64 * 68;               // [64 c][68 d]
    unsigned* Vs = smu + 2 * 64 * 68;           // [64 k][68 d]
    float*    Ps = (float*)(smu + 3 * 64 * 68); // [64 r][68]
    float*    m_s = Ps + 64 * 68;
    float*    l_s = m_s + 64;
    float*    a_s = l_s + 64;

    const int tid  = threadIdx.x;
    const int warp = tid >> 5;
    const int lane = tid & 31;
    const int g = lane >> 2;
    const int t = lane & 3;
    const int wm = warp >> 1;
    const int wn = warp & 1;
    const int qt = blockIdx.x;
    const int b  = blockIdx.y >> 4;
    const int h  = blockIdx.y & 15;
    const int len = g_len[b];

    const float* qb = qkv + (size_t)b * TT * H3 + h * HD;
    const float* kb = qb + HH;
    const float* vb = qb + 2 * HH;

    const int rr = tid >> 4;
    const int d0 = (tid & 15) * 4;

    // Load Q tile (cvt to tf32)
    #pragma unroll
    for (int it = 0; it < 4; it++) {
        const int r = rr + it * 16;
        float4 q4 = *(const float4*)(qb + (size_t)(qt * 64 + r) * H3 + d0);
        Qs[r * 68 + d0 + 0] = f2tf32(q4.x);
        Qs[r * 68 + d0 + 1] = f2tf32(q4.y);
        Qs[r * 68 + d0 + 2] = f2tf32(q4.z);
        Qs[r * 68 + d0 + 3] = f2tf32(q4.w);
    }
    if (tid < 64) { m_s[tid] = -1e30f; l_s[tid] = 0.f; }

    float o[4][4];
    #pragma unroll
    for (int nt = 0; nt < 4; nt++)
        #pragma unroll
        for (int q = 0; q < 4; q++) o[nt][q] = 0.f;

    const int kt_max = min(qt, (len - 1) >> 6);

    // prefetch kt=0 K/V into registers
    float4 kreg[4], vreg[4];
    #pragma unroll
    for (int it = 0; it < 4; it++) {
        const int c = rr + it * 16;
        kreg[it] = *(const float4*)(kb + (size_t)c * H3 + d0);
        vreg[it] = *(const float4*)(vb + (size_t)c * H3 + d0);
    }
    __syncthreads();

    for (int kt = 0; kt <= kt_max; kt++) {
        // commit prefetched K/V to smem
        #pragma unroll
        for (int it = 0; it < 4; it++) {
            const int c = rr + it * 16;
            Ks[c * 68 + d0 + 0] = f2tf32(kreg[it].x);
            Ks[c * 68 + d0 + 1] = f2tf32(kreg[it].y);
            Ks[c * 68 + d0 + 2] = f2tf32(kreg[it].z);
            Ks[c * 68 + d0 + 3] = f2tf32(kreg[it].w);
            Vs[c * 68 + d0 + 0] = f2tf32(vreg[it].x);
            Vs[c * 68 + d0 + 1] = f2tf32(vreg[it].y);
            Vs[c * 68 + d0 + 2] = f2tf32(vreg[it].z);
            Vs[c * 68 + d0 + 3] = f2tf32(vreg[it].w);
        }
        __syncthreads();

        // prefetch next tile (in flight across S-MMA + softmax + PV)
        if (kt < kt_max) {
            #pragma unroll
            for (int it = 0; it < 4; it++) {
                const int c = (kt + 1) * 64 + rr + it * 16;
                kreg[it] = *(const float4*)(kb + (size_t)c * H3 + d0);
                vreg[it] = *(const float4*)(vb + (size_t)c * H3 + d0);
            }
        }

        // S = Q @ K^T via MMA
        float s[4][4];
        #pragma unroll
        for (int nt = 0; nt < 4; nt++)
            #pragma unroll
            for (int q = 0; q < 4; q++) s[nt][q] = 0.f;

        #pragma unroll
        for (int k0 = 0; k0 < 64; k0 += 8) {
            unsigned af[4];
            const int r0 = wm * 16;
            af[0] = Qs[(r0 + g) * 68 + k0 + t];
            af[1] = Qs[(r0 + g + 8) * 68 + k0 + t];
            af[2] = Qs[(r0 + g) * 68 + k0 + t + 4];
            af[3] = Qs[(r0 + g + 8) * 68 + k0 + t + 4];
            #pragma unroll
            for (int nt = 0; nt < 4; nt++) {
                const int c = wn * 32 + nt * 8 + g;
                unsigned bf[2] = { Ks[c * 68 + k0 + t], Ks[c * 68 + k0 + t + 4] };
                mma_tf32(s[nt], af, bf);
            }
        }

        // scale + mask -> Ps
        {
            const int r0 = wm * 16 + g;
            const int q0 = qt * 64;
            #pragma unroll
            for (int nt = 0; nt < 4; nt++) {
                const int c0 = wn * 32 + nt * 8 + 2 * t;
                const int kc = kt * 64 + c0;
                Ps[r0 * 68 + c0] =
                    (kc <= q0 + r0 && kc < len) ? s[nt][0] * 0.125f : -1e30f;
                Ps[r0 * 68 + c0 + 1] =
                    (kc + 1 <= q0 + r0 && kc + 1 < len) ? s[nt][1] * 0.125f : -1e30f;
                Ps[(r0 + 8) * 68 + c0] =
                    (kc <= q0 + r0 + 8 && kc < len) ? s[nt][2] * 0.125f : -1e30f;
                Ps[(r0 + 8) * 68 + c0 + 1] =
                    (kc + 1 <= q0 + r0 + 8 && kc + 1 < len) ? s[nt][3] * 0.125f : -1e30f;
            }
        }
        __syncthreads();

        // online softmax (4 lanes per row); probs pre-rounded to tf32 bits
        {
            const int r = tid >> 2, qq = tid & 3;
            float* prow = Ps + r * 68 + qq * 16;
            float mx = -1e30f;
            #pragma unroll
            for (int c = 0; c < 16; c++) mx = fmaxf(mx, prow[c]);
            mx = fmaxf(mx, __shfl_xor_sync(0xffffffffu, mx, 1));
            mx = fmaxf(mx, __shfl_xor_sync(0xffffffffu, mx, 2));
            const float mo = m_s[r];
            const float mn = fmaxf(mo, mx);
            float sum = 0.f;
            #pragma unroll
            for (int c = 0; c < 16; c++) {
                float e = __expf(prow[c] - mn);
                prow[c] = __uint_as_float(f2tf32(e));
                sum += e;
            }
            sum += __shfl_xor_sync(0xffffffffu, sum, 1);
            sum += __shfl_xor_sync(0xffffffffu, sum, 2);
            if (qq == 0) {
                float a = __expf(mo - mn);
                a_s[r] = a;
                l_s[r] = l_s[r] * a + sum;
                m_s[r] = mn;
            }
        }
        __syncthreads();

        // rescale O
        {
            const float a0 = a_s[wm * 16 + g];
            const float a1 = a_s[wm * 16 + g + 8];
            #pragma unroll
            for (int nt = 0; nt < 4; nt++) {
                o[nt][0] *= a0; o[nt][1] *= a0;
                o[nt][2] *= a1; o[nt][3] *= a1;
            }
        }

        // O += P @ V via MMA
        {
            const unsigned* Pu = (const unsigned*)Ps;
            #pragma unroll
            for (int k0 = 0; k0 < 64; k0 += 8) {
                unsigned af[4];
                const int r0 = wm * 16;
                af[0] = Pu[(r0 + g) * 68 + k0 + t];
                af[1] = Pu[(r0 + g + 8) * 68 + k0 + t];
                af[2] = Pu[(r0 + g) * 68 + k0 + t + 4];
                af[3] = Pu[(r0 + g + 8) * 68 + k0 + t + 4];
                #pragma unroll
                for (int nt = 0; nt < 4; nt++) {
                    const int c = wn * 32 + nt * 8 + g;
                    unsigned bf[2] = { Vs[(k0 + t) * 68 + c],
                                       Vs[(k0 + t + 4) * 68 + c] };
                    mma_tf32(o[nt], af, bf);
                }
            }
        }
        __syncthreads();
    }

    // epilogue: normalize, write (B,T,H)
    {
        const int r0 = wm * 16 + g;
        const float inv0 = 1.f / l_s[r0];
        const float inv1 = 1.f / l_s[r0 + 8];
        float* ob = att + (size_t)b * TT * HH + (size_t)(qt * 64) * HH + h * HD;
        #pragma unroll
        for (int nt = 0; nt < 4; nt++) {
            const int c = wn * 32 + nt * 8 + 2 * t;
            float2 v0 = { o[nt][0] * inv0, o[nt][1] * inv0 };
            float2 v1 = { o[nt][2] * inv1, o[nt][3] * inv1 };
            *(float2*)&ob[(size_t)r0 * HH + c]       = v0;
            *(float2*)&ob[(size_t)(r0 + 8) * HH + c] = v1;
        }
    }
}

// ---------------------------------------------------------------------------

static const int ATTN_SMEM = (4 * 64 * 68 + 3 * 64) * 4;  // 70400 B

extern "C" void kernel_launch(void* const* d_in, const int* in_sizes, int n_in,
                              void* d_out, int out_size)
{
    const float*         inp   = (const float*)d_in[0];
    const unsigned char* mask  = (const unsigned char*)d_in[1];
    const float*         w_qkv = (const float*)d_in[2];
    const float*         b_qkv = (const float*)d_in[3];
    const float*         w_out = (const float*)d_in[4];
    const float*         b_out = (const float*)d_in[5];
    float*               out   = (float*)d_out;

    float *qkv_p, *att_p;
    cudaGetSymbolAddress((void**)&qkv_p, g_qkv);
    cudaGetSymbolAddress((void**)&att_p, g_att);
    cudaFuncSetAttribute(attn_mma,
                         cudaFuncAttributeMaxDynamicSharedMemorySize, ATTN_SMEM);

    len_kernel<<<BB, 256>>>(mask);
    tgemm_bias<<<dim3(H3 / 128, (BB * TT) / 128), 256>>>(
        inp, w_qkv, b_qkv, qkv_p, BB * TT, H3, HH);
    attn_mma<<<dim3(TT / 64, BB * NH), 256, ATTN_SMEM>>>(qkv_p, att_p);
    tgemm_bias<<<dim3(HH / 128, (BB * TT) / 128), 256>>>(
        att_p, w_out, b_out, out, BB * TT, HH, HH);
}